// round 3
// baseline (speedup 1.0000x reference)
#include <cuda_runtime.h>
#include <cuda_bf16.h>
#include <float.h>

#define NB 8
#define NS 4096
#define ND 256
#define NR 512
#define NC 2048
#define S1 (NS + 1)

// ---------------- scratch (device globals; no allocation allowed) -----------
__device__ float  g_t[NB * NR];                 // cls . cls_w
__device__ float  g_P[NB * ND * NR];            // softmax probs [b][d][r]
__device__ float  g_embT[(size_t)NB * NC * ND]; // emb_b transposed [b][c][d]
__device__ float  g_esq[NB * NC];               // ||emb_b[:,c]||^2
__device__ float  g_qsq[NB * NS];               // ||pos[s]||^2
__device__ int    g_idx[NB * NS];               // argmin indices
__device__ int    g_hist[NB * NC];              // per-batch histogram
__device__ double g_msep[256];                  // MSE partial sums

// ---------------- zero per-launch accumulators ------------------------------
__global__ void k_zero() {
    int i = blockIdx.x * blockDim.x + threadIdx.x;
    if (i < NB * NC) g_hist[i] = 0;
    if (i < 256) g_msep[i] = 0.0;
}

// ---------------- t[b,r] = sum_d cls[b,d] * cls_w[d,r] ----------------------
__global__ void k_t(const float* __restrict__ x, const float* __restrict__ cls_w) {
    int b = blockIdx.x;
    int r = threadIdx.x;  // 512
    __shared__ float cls[ND];
    if (r < ND) cls[r] = x[(size_t)b * S1 * ND + r];
    __syncthreads();
    float acc = 0.f;
#pragma unroll 8
    for (int d = 0; d < ND; d++) acc = fmaf(cls[d], cls_w[d * NR + r], acc);
    g_t[b * NR + r] = acc;
}

// ---------------- softmax over R per (b,d):  P = softmax(cls[b,d]*t + b) ----
__global__ void k_softmax(const float* __restrict__ x, const float* __restrict__ cls_b) {
    int d = blockIdx.x, b = blockIdx.y;
    int r = threadIdx.x;  // 512 threads
    float clsd = x[(size_t)b * S1 * ND + d];
    float logit = fmaf(clsd, g_t[b * NR + r], cls_b[r]);

    __shared__ float sred[16];
    float m = logit;
#pragma unroll
    for (int o = 16; o; o >>= 1) m = fmaxf(m, __shfl_xor_sync(0xffffffffu, m, o));
    if ((r & 31) == 0) sred[r >> 5] = m;
    __syncthreads();
    if (r < 32) {
        float v = (r < 16) ? sred[r] : -FLT_MAX;
#pragma unroll
        for (int o = 16; o; o >>= 1) v = fmaxf(v, __shfl_xor_sync(0xffffffffu, v, o));
        if (r == 0) sred[0] = v;
    }
    __syncthreads();
    m = sred[0];
    float e = expf(logit - m);
    __syncthreads();
    float s = e;
#pragma unroll
    for (int o = 16; o; o >>= 1) s += __shfl_xor_sync(0xffffffffu, s, o);
    if ((r & 31) == 0) sred[r >> 5] = s;
    __syncthreads();
    if (r < 32) {
        float v = (r < 16) ? sred[r] : 0.f;
#pragma unroll
        for (int o = 16; o; o >>= 1) v += __shfl_xor_sync(0xffffffffu, v, o);
        if (r == 0) sred[0] = v;
    }
    __syncthreads();
    g_P[((size_t)b * ND + d) * NR + r] = e / sred[0];
}

// ---------------- embT[b][c][d] = sum_r P[b][d][r] * emb[r][c] --------------
__global__ __launch_bounds__(256) void k_emb(const float* __restrict__ emb) {
    int b = blockIdx.z;
    int c0 = blockIdx.x * 64, d0 = blockIdx.y * 64;
    const float* P = g_P + (size_t)b * ND * NR;  // [d][r]

    __shared__ float sP[16][64];  // [r][d]
    __shared__ float sE[16][64];  // [r][c]

    int tid = threadIdx.x;
    int tx = tid & 15, ty = tid >> 4;
    int ld_ = tid >> 2;
    int lr  = (tid & 3) << 2;
    int er  = tid >> 4;
    int ec  = (tid & 15) << 2;

    float acc[4][4];
#pragma unroll
    for (int i = 0; i < 4; i++)
#pragma unroll
        for (int j = 0; j < 4; j++) acc[i][j] = 0.f;

    for (int r0 = 0; r0 < NR; r0 += 16) {
        float4 p4 = *(const float4*)(P + (size_t)(d0 + ld_) * NR + r0 + lr);
        float4 e4 = *(const float4*)(emb + (size_t)(r0 + er) * NC + c0 + ec);
        __syncthreads();
        sP[lr + 0][ld_] = p4.x; sP[lr + 1][ld_] = p4.y;
        sP[lr + 2][ld_] = p4.z; sP[lr + 3][ld_] = p4.w;
        *(float4*)&sE[er][ec] = e4;
        __syncthreads();
#pragma unroll
        for (int kk = 0; kk < 16; kk++) {
            float4 av = *(const float4*)&sP[kk][ty << 2];
            float4 bv = *(const float4*)&sE[kk][tx << 2];
            float a[4] = {av.x, av.y, av.z, av.w};
            float bb[4] = {bv.x, bv.y, bv.z, bv.w};
#pragma unroll
            for (int i = 0; i < 4; i++)
#pragma unroll
                for (int j = 0; j < 4; j++) acc[i][j] = fmaf(a[i], bb[j], acc[i][j]);
        }
    }
#pragma unroll
    for (int j = 0; j < 4; j++) {
        int c = c0 + (tx << 2) + j;
        float4 v = make_float4(acc[0][j], acc[1][j], acc[2][j], acc[3][j]);
        *(float4*)(g_embT + ((size_t)b * NC + c) * ND + d0 + (ty << 2)) = v;
    }
}

// ---------------- e_sq[b][c] = sum_d embT[b][c][d]^2 ------------------------
__global__ void k_esq() {
    int row = blockIdx.x * 8 + (threadIdx.x >> 5);
    int lane = threadIdx.x & 31;
    const float* p = g_embT + (size_t)row * ND;
    float s = 0.f;
#pragma unroll
    for (int i = lane; i < ND; i += 32) { float v = p[i]; s = fmaf(v, v, s); }
#pragma unroll
    for (int o = 16; o; o >>= 1) s += __shfl_xor_sync(0xffffffffu, s, o);
    if (lane == 0) g_esq[row] = s;
}

// ---------------- q_sq[b][s] = sum_d pos[s][d]^2 ----------------------------
__global__ void k_qsq(const float* __restrict__ x) {
    int row = blockIdx.x * 8 + (threadIdx.x >> 5);  // b*NS + s
    int lane = threadIdx.x & 31;
    int b = row >> 12, s = row & (NS - 1);
    const float* p = x + ((size_t)b * S1 + 1 + s) * ND;
    float acc = 0.f;
#pragma unroll
    for (int i = lane; i < ND; i += 32) { float v = p[i]; acc = fmaf(v, v, acc); }
#pragma unroll
    for (int o = 16; o; o >>= 1) acc += __shfl_xor_sync(0xffffffffu, acc, o);
    if (lane == 0) g_qsq[row] = acc;
}

// ---------------- main fused GEMM + argmin ----------------------------------
// dist[s][c] = (q_sq[s] - 2*dot) + e_sq[c]  (reference op order, fp32 grid)
// argmin over c, lowest index on ties
__global__ __launch_bounds__(256) void k_argmin(const float* __restrict__ x) {
    int b = blockIdx.y;
    int s0 = blockIdx.x * 64;
    const float* pos  = x + ((size_t)b * S1 + 1) * ND;
    const float* embT = g_embT + (size_t)b * NC * ND;
    const float* esq  = g_esq + b * NC;

    __shared__ float sA[16][64];   // [k][s]
    __shared__ float sB[16][64];   // [k][c]
    __shared__ float rV[64][16];
    __shared__ int   rI[64][16];

    int tid = threadIdx.x;
    int tx = tid & 15, ty = tid >> 4;
    int ls = tid >> 2;
    int lk = (tid & 3) << 2;

    float qs[4];
#pragma unroll
    for (int i = 0; i < 4; i++) qs[i] = g_qsq[b * NS + s0 + (ty << 2) + i];

    float minv[4]; int mini[4];
#pragma unroll
    for (int i = 0; i < 4; i++) { minv[i] = FLT_MAX; mini[i] = 0; }

    for (int c0 = 0; c0 < NC; c0 += 64) {
        float acc[4][4];
#pragma unroll
        for (int i = 0; i < 4; i++)
#pragma unroll
            for (int j = 0; j < 4; j++) acc[i][j] = 0.f;

        for (int k0 = 0; k0 < ND; k0 += 16) {
            float4 a4 = *(const float4*)(pos  + (size_t)(s0 + ls) * ND + k0 + lk);
            float4 b4 = *(const float4*)(embT + (size_t)(c0 + ls) * ND + k0 + lk);
            __syncthreads();
            sA[lk + 0][ls] = a4.x; sA[lk + 1][ls] = a4.y;
            sA[lk + 2][ls] = a4.z; sA[lk + 3][ls] = a4.w;
            sB[lk + 0][ls] = b4.x; sB[lk + 1][ls] = b4.y;
            sB[lk + 2][ls] = b4.z; sB[lk + 3][ls] = b4.w;
            __syncthreads();
#pragma unroll
            for (int kk = 0; kk < 16; kk++) {
                float4 av = *(const float4*)&sA[kk][ty << 2];
                float4 bv = *(const float4*)&sB[kk][tx << 2];
                float a[4]  = {av.x, av.y, av.z, av.w};
                float bb[4] = {bv.x, bv.y, bv.z, bv.w};
#pragma unroll
                for (int i = 0; i < 4; i++)
#pragma unroll
                    for (int j = 0; j < 4; j++)
                        acc[i][j] = fmaf(a[i], bb[j], acc[i][j]);
            }
        }
        // dist = (q_sq - 2*dot) + e_sq  -- reference op order, same fp32 grid
#pragma unroll
        for (int j = 0; j < 4; j++) {
            int c = c0 + (tx << 2) + j;
            float e = esq[c];
#pragma unroll
            for (int i = 0; i < 4; i++) {
                float sc = (qs[i] - 2.f * acc[i][j]) + e;
                if (sc < minv[i]) { minv[i] = sc; mini[i] = c; }
            }
        }
    }
#pragma unroll
    for (int i = 0; i < 4; i++) { rV[(ty << 2) + i][tx] = minv[i]; rI[(ty << 2) + i][tx] = mini[i]; }
    __syncthreads();
    if (tid < 64) {
        float bv = rV[tid][0]; int bi = rI[tid][0];
#pragma unroll
        for (int t = 1; t < 16; t++) {
            float v = rV[tid][t]; int ii = rI[tid][t];
            if (v < bv || (v == bv && ii < bi)) { bv = v; bi = ii; }
        }
        g_idx[b * NS + s0 + tid] = bi;
    }
}

// ---------------- gather + output + MSE partials + histogram ----------------
__global__ void k_gather(const float* __restrict__ x, float* __restrict__ out) {
    int tkn = blockIdx.x;        // b*S + s
    int b = tkn >> 12;
    int s = tkn & (NS - 1);
    int d = threadIdx.x;         // 256
    int idx = g_idx[tkn];
    float q = g_embT[((size_t)b * NC + idx) * ND + d];
    float p = x[((size_t)b * S1 + 1 + s) * ND + d];
    out[((size_t)b * S1 + 1 + s) * ND + d] = q;
    float diff = q - p;
    float v = diff * diff;
#pragma unroll
    for (int o = 16; o; o >>= 1) v += __shfl_xor_sync(0xffffffffu, v, o);
    __shared__ float sw[8];
    if ((d & 31) == 0) sw[d >> 5] = v;
    __syncthreads();
    if (d == 0) {
        float tot = 0.f;
#pragma unroll
        for (int i = 0; i < 8; i++) tot += sw[i];
        atomicAdd(&g_msep[blockIdx.x & 255], (double)tot);
        atomicAdd(&g_hist[b * NC + idx], 1);
    }
}

// ---------------- copy cls tokens to output row 0 ---------------------------
__global__ void k_cls(const float* __restrict__ x, float* __restrict__ out) {
    int i = blockIdx.x * blockDim.x + threadIdx.x;  // 2048
    int b = i >> 8, d = i & 255;
    out[(size_t)b * S1 * ND + d] = x[(size_t)b * S1 * ND + d];
}

// ---------------- finalize scalars ------------------------------------------
__global__ void k_final(float* __restrict__ out) {
    int t = threadIdx.x;  // 256
    __shared__ double sd[256];
    sd[t] = g_msep[t];
    __syncthreads();
    for (int o = 128; o; o >>= 1) { if (t < o) sd[t] += sd[t + o]; __syncthreads(); }
    float mse = (float)(sd[0] / (double)((size_t)NB * NS * ND));

    __shared__ float sf[256];
    float pacc = 0.f;
    for (int b = 0; b < NB; b++) {
        float h = 0.f;
        for (int c = t; c < NC; c += 256) {
            float p = (float)g_hist[b * NC + c] / (float)NS;
            h += p * logf(p + 1e-10f);
        }
        sf[t] = h;
        __syncthreads();
        for (int o = 128; o; o >>= 1) { if (t < o) sf[t] += sf[t + o]; __syncthreads(); }
        if (t == 0) pacc += expf(-sf[0]);
        __syncthreads();
    }
    if (t == 0) {
        size_t Q = (size_t)NB * S1 * ND;
        out[Q + 0] = pacc / (float)NB;      // perplexity
        out[Q + 1] = mse;                    // e_latent_loss
        out[Q + 2] = mse;                    // q_latent_loss
        out[Q + 3] = fmaf(mse, 0.25f, mse);  // vq_loss
    }
}

// ---------------- launch -----------------------------------------------------
extern "C" void kernel_launch(void* const* d_in, const int* in_sizes, int n_in,
                              void* d_out, int out_size) {
    const float* x     = (const float*)d_in[0];
    const float* emb   = (const float*)d_in[1];
    const float* cls_w = (const float*)d_in[2];
    const float* cls_b = (const float*)d_in[3];
    float* out = (float*)d_out;
    (void)in_sizes; (void)n_in; (void)out_size;

    k_zero<<<64, 256>>>();
    k_t<<<NB, NR>>>(x, cls_w);
    k_softmax<<<dim3(ND, NB), NR>>>(x, cls_b);
    k_emb<<<dim3(NC / 64, ND / 64, NB), 256>>>(emb);
    k_esq<<<NB * NC / 8, 256>>>();
    k_qsq<<<NB * NS / 8, 256>>>(x);
    k_argmin<<<dim3(NS / 64, NB), 256>>>(x);
    k_gather<<<NB * NS, 256>>>(x, out);
    k_cls<<<8, 256>>>(x, out);
    k_final<<<1, 256>>>(out);
}

// round 4
// speedup vs baseline: 1.3232x; 1.3232x over previous
#include <cuda_runtime.h>
#include <float.h>

#define NB 8
#define NS 4096
#define ND 256
#define NR 512
#define NC 2048
#define S1 (NS + 1)

#define BK 16
#define LDSP 132   // padded smem row stride (floats); 132*4 % 16 == 0

// ---------------- scratch ----------------------------------------------------
__device__ float  g_t[NB * NR];
__device__ float  g_P[NB * ND * NR];
__device__ float  g_embT[(size_t)NB * NC * ND];
__device__ float  g_esq[NB * NC];
__device__ float  g_qsq[NB * NS];
__device__ int    g_idx[NB * NS];
__device__ int    g_hist[NB * NC];
__device__ double g_msep[256];

// ---------------- f32x2 helpers ----------------------------------------------
__device__ __forceinline__ unsigned long long pack2(float lo, float hi) {
    unsigned long long r;
    asm("mov.b64 %0, {%1, %2};" : "=l"(r) : "f"(lo), "f"(hi));
    return r;
}
__device__ __forceinline__ void unpack2(unsigned long long v, float& lo, float& hi) {
    asm("mov.b64 {%0, %1}, %2;" : "=f"(lo), "=f"(hi) : "l"(v));
}
#define FMA2(d, a, b) asm("fma.rn.f32x2 %0, %1, %2, %0;" : "+l"(d) : "l"(a), "l"(b))

// inner product over one BK-deep smem tile; acc[4][8] = row-pairs x 8 cols
__device__ __forceinline__ void mma_tile(unsigned aAddr, unsigned bAddr,
                                         unsigned long long acc[4][8]) {
#pragma unroll
    for (int kk = 0; kk < BK; kk++) {
        unsigned long long a01, a23, a45, a67;
        asm("ld.shared.v2.b64 {%0,%1}, [%2];"
            : "=l"(a01), "=l"(a23) : "r"(aAddr + kk * (LDSP * 4)));
        asm("ld.shared.v2.b64 {%0,%1}, [%2];"
            : "=l"(a45), "=l"(a67) : "r"(aAddr + kk * (LDSP * 4) + 16));
        float b0, b1, b2, b3, b4, b5, b6, b7;
        asm("ld.shared.v4.b32 {%0,%1,%2,%3}, [%4];"
            : "=f"(b0), "=f"(b1), "=f"(b2), "=f"(b3) : "r"(bAddr + kk * (LDSP * 4)));
        asm("ld.shared.v4.b32 {%0,%1,%2,%3}, [%4];"
            : "=f"(b4), "=f"(b5), "=f"(b6), "=f"(b7) : "r"(bAddr + kk * (LDSP * 4) + 16));
        float bs[8] = {b0, b1, b2, b3, b4, b5, b6, b7};
#pragma unroll
        for (int j = 0; j < 8; j++) {
            unsigned long long bb = pack2(bs[j], bs[j]);
            FMA2(acc[0][j], a01, bb);
            FMA2(acc[1][j], a23, bb);
            FMA2(acc[2][j], a45, bb);
            FMA2(acc[3][j], a67, bb);
        }
    }
}

// ---------------- zero per-launch accumulators ------------------------------
__global__ void k_zero() {
    int i = blockIdx.x * blockDim.x + threadIdx.x;
    if (i < NB * NC) g_hist[i] = 0;
    if (i < 256) g_msep[i] = 0.0;
}

// ---------------- t[b,r] = sum_d cls[b,d] * cls_w[d,r] ----------------------
__global__ void k_t(const float* __restrict__ x, const float* __restrict__ cls_w) {
    int b = blockIdx.x;
    int r = threadIdx.x;  // 512
    __shared__ float cls[ND];
    if (r < ND) cls[r] = x[(size_t)b * S1 * ND + r];
    __syncthreads();
    float acc = 0.f;
#pragma unroll 8
    for (int d = 0; d < ND; d++) acc = fmaf(cls[d], cls_w[d * NR + r], acc);
    g_t[b * NR + r] = acc;
}

// ---------------- softmax over R per (b,d) ----------------------------------
__global__ void k_softmax(const float* __restrict__ x, const float* __restrict__ cls_b) {
    int d = blockIdx.x, b = blockIdx.y;
    int r = threadIdx.x;  // 512 threads
    float clsd = x[(size_t)b * S1 * ND + d];
    float logit = fmaf(clsd, g_t[b * NR + r], cls_b[r]);

    __shared__ float sred[16];
    float m = logit;
#pragma unroll
    for (int o = 16; o; o >>= 1) m = fmaxf(m, __shfl_xor_sync(0xffffffffu, m, o));
    if ((r & 31) == 0) sred[r >> 5] = m;
    __syncthreads();
    if (r < 32) {
        float v = (r < 16) ? sred[r] : -FLT_MAX;
#pragma unroll
        for (int o = 16; o; o >>= 1) v = fmaxf(v, __shfl_xor_sync(0xffffffffu, v, o));
        if (r == 0) sred[0] = v;
    }
    __syncthreads();
    m = sred[0];
    float e = expf(logit - m);
    __syncthreads();
    float s = e;
#pragma unroll
    for (int o = 16; o; o >>= 1) s += __shfl_xor_sync(0xffffffffu, s, o);
    if ((r & 31) == 0) sred[r >> 5] = s;
    __syncthreads();
    if (r < 32) {
        float v = (r < 16) ? sred[r] : 0.f;
#pragma unroll
        for (int o = 16; o; o >>= 1) v += __shfl_xor_sync(0xffffffffu, v, o);
        if (r == 0) sred[0] = v;
    }
    __syncthreads();
    g_P[((size_t)b * ND + d) * NR + r] = e / sred[0];
}

// ---------------- embT[b][c][d] = sum_r P[b][d][r] * emb[r][c] --------------
// 128(d) x 128(c) tile, 256 threads, 8x8 micro via f32x2, double-buffered
__global__ __launch_bounds__(256) void k_emb(const float* __restrict__ emb) {
    __shared__ __align__(16) float smem[4 * BK * LDSP];
    int b = blockIdx.z;
    int c0 = blockIdx.x * 128, d0 = blockIdx.y * 128;
    const float* P = g_P + (size_t)b * ND * NR;  // [d][r]

    int tid = threadIdx.x;
    int tx = tid & 15, ty = tid >> 4;
    int arow = tid >> 1, ak = (tid & 1) << 3;     // A loader: d-row, k-offset
    int brow = tid >> 4, bcol = (tid & 15) << 3;  // B loader: k-row, c-offset

    unsigned sbase = (unsigned)__cvta_generic_to_shared(smem);
    unsigned aAddr0 = sbase + (unsigned)(ty * 8) * 4;
    unsigned bAddr0 = sbase + (unsigned)(2 * BK * LDSP + tx * 8) * 4;
    const unsigned bufStride = BK * LDSP * 4;

    const float* pa = P + (size_t)(d0 + arow) * NR + ak;
    const float* pb = emb + (size_t)brow * NC + c0 + bcol;

    unsigned long long acc[4][8];
#pragma unroll
    for (int p = 0; p < 4; p++)
#pragma unroll
        for (int j = 0; j < 8; j++) acc[p][j] = 0ull;

    // prologue: k-tile 0 -> buf0
    float4 a0 = *(const float4*)(pa);
    float4 a1 = *(const float4*)(pa + 4);
    float4 b0 = *(const float4*)(pb);
    float4 b1 = *(const float4*)(pb + 4);
    {
        float av[8] = {a0.x, a0.y, a0.z, a0.w, a1.x, a1.y, a1.z, a1.w};
#pragma unroll
        for (int i = 0; i < 8; i++) smem[(ak + i) * LDSP + arow] = av[i];
        *(float4*)&smem[2 * BK * LDSP + brow * LDSP + bcol] = b0;
        *(float4*)&smem[2 * BK * LDSP + brow * LDSP + bcol + 4] = b1;
    }
    __syncthreads();

    const int NKT = NR / BK;  // 32
#pragma unroll 1
    for (int kt = 0; kt < NKT; kt++) {
        if (kt + 1 < NKT) {
            a0 = *(const float4*)(pa + (kt + 1) * BK);
            a1 = *(const float4*)(pa + (kt + 1) * BK + 4);
            b0 = *(const float4*)(pb + (size_t)(kt + 1) * BK * NC);
            b1 = *(const float4*)(pb + (size_t)(kt + 1) * BK * NC + 4);
        }
        unsigned off = (unsigned)(kt & 1) * bufStride;
        mma_tile(aAddr0 + off, bAddr0 + off, acc);
        if (kt + 1 < NKT) {
            int nb = (kt + 1) & 1;
            float* dA = smem + nb * BK * LDSP;
            float* dB = smem + (2 + nb) * BK * LDSP;
            float av[8] = {a0.x, a0.y, a0.z, a0.w, a1.x, a1.y, a1.z, a1.w};
#pragma unroll
            for (int i = 0; i < 8; i++) dA[(ak + i) * LDSP + arow] = av[i];
            *(float4*)&dB[brow * LDSP + bcol] = b0;
            *(float4*)&dB[brow * LDSP + bcol + 4] = b1;
            __syncthreads();
        }
    }

    // epilogue: write embT[c][d]
#pragma unroll
    for (int j = 0; j < 8; j++) {
        int c = c0 + tx * 8 + j;
        float v0, v1, v2, v3, v4, v5, v6, v7;
        unpack2(acc[0][j], v0, v1);
        unpack2(acc[1][j], v2, v3);
        unpack2(acc[2][j], v4, v5);
        unpack2(acc[3][j], v6, v7);
        float* dst = g_embT + ((size_t)b * NC + c) * ND + d0 + ty * 8;
        *(float4*)dst = make_float4(v0, v1, v2, v3);
        *(float4*)(dst + 4) = make_float4(v4, v5, v6, v7);
    }
}

// ---------------- e_sq[b][c] = sum_d embT[b][c][d]^2 ------------------------
__global__ void k_esq() {
    int row = blockIdx.x * 8 + (threadIdx.x >> 5);
    int lane = threadIdx.x & 31;
    const float* p = g_embT + (size_t)row * ND;
    float s = 0.f;
#pragma unroll
    for (int i = lane; i < ND; i += 32) { float v = p[i]; s = fmaf(v, v, s); }
#pragma unroll
    for (int o = 16; o; o >>= 1) s += __shfl_xor_sync(0xffffffffu, s, o);
    if (lane == 0) g_esq[row] = s;
}

// ---------------- q_sq[b][s] = sum_d pos[s][d]^2 ----------------------------
__global__ void k_qsq(const float* __restrict__ x) {
    int row = blockIdx.x * 8 + (threadIdx.x >> 5);  // b*NS + s
    int lane = threadIdx.x & 31;
    int b = row >> 12, s = row & (NS - 1);
    const float* p = x + ((size_t)b * S1 + 1 + s) * ND;
    float acc = 0.f;
#pragma unroll
    for (int i = lane; i < ND; i += 32) { float v = p[i]; acc = fmaf(v, v, acc); }
#pragma unroll
    for (int o = 16; o; o >>= 1) acc += __shfl_xor_sync(0xffffffffu, acc, o);
    if (lane == 0) g_qsq[row] = acc;
}

// ---------------- fused dist GEMM + argmin ----------------------------------
// 128(s) x 128(c) tile, f32x2 micro-kernel; block sweeps all C for its rows
__global__ __launch_bounds__(256) void k_argmin(const float* __restrict__ x) {
    __shared__ __align__(16) float smem[4 * BK * LDSP];
    int b = blockIdx.y;
    int s0 = blockIdx.x * 128;
    const float* pos  = x + ((size_t)b * S1 + 1) * ND;
    const float* embT = g_embT + (size_t)b * NC * ND;
    const float* esq  = g_esq + b * NC;
    const float* qsq  = g_qsq + b * NS;

    int tid = threadIdx.x;
    int tx = tid & 15, ty = tid >> 4;
    int lrow = tid >> 1, lk = (tid & 1) << 3;

    unsigned sbase = (unsigned)__cvta_generic_to_shared(smem);
    unsigned aAddr0 = sbase + (unsigned)(ty * 8) * 4;
    unsigned bAddr0 = sbase + (unsigned)(2 * BK * LDSP + tx * 8) * 4;
    const unsigned bufStride = BK * LDSP * 4;

    float qs[8];
#pragma unroll
    for (int i = 0; i < 8; i++) qs[i] = qsq[s0 + ty * 8 + i];

    float minv[8]; int mini[8];
#pragma unroll
    for (int i = 0; i < 8; i++) { minv[i] = FLT_MAX; mini[i] = 0; }

    const float* pa = pos + (size_t)(s0 + lrow) * ND + lk;

#pragma unroll 1
    for (int c0 = 0; c0 < NC; c0 += 128) {
        const float* pb = embT + (size_t)(c0 + lrow) * ND + lk;

        // prologue: k-tile 0 -> buf0
        float4 a0 = *(const float4*)(pa);
        float4 a1 = *(const float4*)(pa + 4);
        float4 b0 = *(const float4*)(pb);
        float4 b1 = *(const float4*)(pb + 4);
        {
            float av[8] = {a0.x, a0.y, a0.z, a0.w, a1.x, a1.y, a1.z, a1.w};
            float bv[8] = {b0.x, b0.y, b0.z, b0.w, b1.x, b1.y, b1.z, b1.w};
#pragma unroll
            for (int i = 0; i < 8; i++) {
                smem[(lk + i) * LDSP + lrow] = av[i];
                smem[2 * BK * LDSP + (lk + i) * LDSP + lrow] = bv[i];
            }
        }
        __syncthreads();

        unsigned long long acc[4][8];
#pragma unroll
        for (int p = 0; p < 4; p++)
#pragma unroll
            for (int j = 0; j < 8; j++) acc[p][j] = 0ull;

        const int NKT = ND / BK;  // 16
#pragma unroll 1
        for (int kt = 0; kt < NKT; kt++) {
            if (kt + 1 < NKT) {
                a0 = *(const float4*)(pa + (kt + 1) * BK);
                a1 = *(const float4*)(pa + (kt + 1) * BK + 4);
                b0 = *(const float4*)(pb + (kt + 1) * BK);
                b1 = *(const float4*)(pb + (kt + 1) * BK + 4);
            }
            unsigned off = (unsigned)(kt & 1) * bufStride;
            mma_tile(aAddr0 + off, bAddr0 + off, acc);
            if (kt + 1 < NKT) {
                int nb = (kt + 1) & 1;
                float* dA = smem + nb * BK * LDSP;
                float* dB = smem + (2 + nb) * BK * LDSP;
                float av[8] = {a0.x, a0.y, a0.z, a0.w, a1.x, a1.y, a1.z, a1.w};
                float bv[8] = {b0.x, b0.y, b0.z, b0.w, b1.x, b1.y, b1.z, b1.w};
#pragma unroll
                for (int i = 0; i < 8; i++) {
                    dA[(lk + i) * LDSP + lrow] = av[i];
                    dB[(lk + i) * LDSP + lrow] = bv[i];
                }
                __syncthreads();
            }
        }

        // dist = (q_sq - 2*dot) + e_sq  (reference op order); running argmin
#pragma unroll
        for (int j = 0; j < 8; j++) {
            int c = c0 + tx * 8 + j;
            float e = esq[c];
#pragma unroll
            for (int p = 0; p < 4; p++) {
                float d0v, d1v;
                unpack2(acc[p][j], d0v, d1v);
                float sc0 = (qs[2 * p]     - 2.f * d0v) + e;
                float sc1 = (qs[2 * p + 1] - 2.f * d1v) + e;
                if (sc0 < minv[2 * p])     { minv[2 * p] = sc0;     mini[2 * p] = c; }
                if (sc1 < minv[2 * p + 1]) { minv[2 * p + 1] = sc1; mini[2 * p + 1] = c; }
            }
        }
        __syncthreads();  // protect smem reuse (next prologue / reduction)
    }

    // cross-thread reduction: reuse smem
    float* rV = smem;                     // [128][16]
    int*   rI = (int*)(smem + 2048);      // [128][16]
#pragma unroll
    for (int i = 0; i < 8; i++) {
        rV[(ty * 8 + i) * 16 + tx] = minv[i];
        rI[(ty * 8 + i) * 16 + tx] = mini[i];
    }
    __syncthreads();
    if (tid < 128) {
        float bv = rV[tid * 16]; int bi = rI[tid * 16];
#pragma unroll
        for (int t = 1; t < 16; t++) {
            float v = rV[tid * 16 + t]; int ii = rI[tid * 16 + t];
            if (v < bv || (v == bv && ii < bi)) { bv = v; bi = ii; }
        }
        g_idx[b * NS + s0 + tid] = bi;
    }
}

// ---------------- gather + output + MSE partials + histogram ----------------
__global__ void k_gather(const float* __restrict__ x, float* __restrict__ out) {
    int tkn = blockIdx.x;        // b*S + s
    int b = tkn >> 12;
    int s = tkn & (NS - 1);
    int d = threadIdx.x;         // 256
    int idx = g_idx[tkn];
    float q = g_embT[((size_t)b * NC + idx) * ND + d];
    float p = x[((size_t)b * S1 + 1 + s) * ND + d];
    out[((size_t)b * S1 + 1 + s) * ND + d] = q;
    float diff = q - p;
    float v = diff * diff;
#pragma unroll
    for (int o = 16; o; o >>= 1) v += __shfl_xor_sync(0xffffffffu, v, o);
    __shared__ float sw[8];
    if ((d & 31) == 0) sw[d >> 5] = v;
    __syncthreads();
    if (d == 0) {
        float tot = 0.f;
#pragma unroll
        for (int i = 0; i < 8; i++) tot += sw[i];
        atomicAdd(&g_msep[blockIdx.x & 255], (double)tot);
        atomicAdd(&g_hist[b * NC + idx], 1);
    }
}

// ---------------- copy cls tokens to output row 0 ---------------------------
__global__ void k_cls(const float* __restrict__ x, float* __restrict__ out) {
    int i = blockIdx.x * blockDim.x + threadIdx.x;  // 2048
    int b = i >> 8, d = i & 255;
    out[(size_t)b * S1 * ND + d] = x[(size_t)b * S1 * ND + d];
}

// ---------------- finalize scalars ------------------------------------------
__global__ void k_final(float* __restrict__ out) {
    int t = threadIdx.x;  // 256
    __shared__ double sd[256];
    sd[t] = g_msep[t];
    __syncthreads();
    for (int o = 128; o; o >>= 1) { if (t < o) sd[t] += sd[t + o]; __syncthreads(); }
    float mse = (float)(sd[0] / (double)((size_t)NB * NS * ND));

    __shared__ float sf[256];
    float pacc = 0.f;
    for (int b = 0; b < NB; b++) {
        float h = 0.f;
        for (int c = t; c < NC; c += 256) {
            float p = (float)g_hist[b * NC + c] / (float)NS;
            h += p * logf(p + 1e-10f);
        }
        sf[t] = h;
        __syncthreads();
        for (int o = 128; o; o >>= 1) { if (t < o) sf[t] += sf[t + o]; __syncthreads(); }
        if (t == 0) pacc += expf(-sf[0]);
        __syncthreads();
    }
    if (t == 0) {
        size_t Q = (size_t)NB * S1 * ND;
        out[Q + 0] = pacc / (float)NB;      // perplexity
        out[Q + 1] = mse;                    // e_latent_loss
        out[Q + 2] = mse;                    // q_latent_loss
        out[Q + 3] = fmaf(mse, 0.25f, mse);  // vq_loss
    }
}

// ---------------- launch -----------------------------------------------------
extern "C" void kernel_launch(void* const* d_in, const int* in_sizes, int n_in,
                              void* d_out, int out_size) {
    const float* x     = (const float*)d_in[0];
    const float* emb   = (const float*)d_in[1];
    const float* cls_w = (const float*)d_in[2];
    const float* cls_b = (const float*)d_in[3];
    float* out = (float*)d_out;
    (void)in_sizes; (void)n_in; (void)out_size;

    k_zero<<<64, 256>>>();
    k_t<<<NB, NR>>>(x, cls_w);
    k_softmax<<<dim3(ND, NB), NR>>>(x, cls_b);
    k_emb<<<dim3(NC / 128, ND / 128, NB), 256>>>(emb);
    k_esq<<<NB * NC / 8, 256>>>();
    k_qsq<<<NB * NS / 8, 256>>>(x);
    k_argmin<<<dim3(NS / 128, NB), 256>>>(x);
    k_gather<<<NB * NS, 256>>>(x, out);
    k_cls<<<8, 256>>>(x, out);
    k_final<<<1, 256>>>(out);
}